// round 16
// baseline (speedup 1.0000x reference)
#include <cuda_runtime.h>
#include <cuda_bf16.h>
#include <cuda_fp16.h>
#include <cstdint>

#define N_NODES 50000
#define N_EDGES 850000
#define IN_F 512
#define HID_F 256
#define OUT_F 128

// ---------------- device scratch ----------------
__device__ uint32_t g_hw1h[N_NODES * HID_F / 2];   // x @ W1, fp16x2 packed
__device__ uint32_t g_hw2h[N_NODES * OUT_F / 2];   // h @ W2, fp16x2 packed
__device__ uint32_t g_xh[N_NODES * IN_F / 2];      // x as fp16x2 pairs along K
__device__ uint32_t g_hh[N_NODES * HID_F / 2];     // h as fp16x2 (written by agg1)
__device__ uint32_t g_w1thi[HID_F * (IN_F / 2)];   // W1^T [N=256][K2=256] fp16 hi
__device__ uint32_t g_w1tlo[HID_F * (IN_F / 2)];   // fp16 lo (residual)
__device__ uint32_t g_w2thi[OUT_F * (HID_F / 2)];  // W2^T [N=128][K2=128]
__device__ uint32_t g_w2tlo[OUT_F * (HID_F / 2)];
__device__ float    g_invdeg[N_NODES];
__device__ int      g_deg[N_NODES];
__device__ int      g_rowptr[N_NODES + 1];
__device__ int      g_pos[N_NODES];
__device__ int      g_esrc[N_EDGES];
__device__ float    g_ew[N_EDGES];

// ---------------- fp16 helpers ----------------
__device__ __forceinline__ uint32_t f16pair(float a, float b) {
    __half2 p = __floats2half2_rn(a, b);
    return *reinterpret_cast<uint32_t*>(&p);
}
__device__ __forceinline__ uint32_t split_pair_f16(float a, float b, uint32_t& lo_out) {
    __half ha = __float2half_rn(a);
    __half hb = __float2half_rn(b);
    float ra = a - __half2float(ha);
    float rb = b - __half2float(hb);
    __half la = __float2half_rn(ra);
    __half lb = __float2half_rn(rb);
    uint16_t uha = *reinterpret_cast<uint16_t*>(&ha);
    uint16_t uhb = *reinterpret_cast<uint16_t*>(&hb);
    uint16_t ula = *reinterpret_cast<uint16_t*>(&la);
    uint16_t ulb = *reinterpret_cast<uint16_t*>(&lb);
    lo_out = (uint32_t)ula | ((uint32_t)ulb << 16);
    return (uint32_t)uha | ((uint32_t)uhb << 16);
}

// ---------------- fused prep: count_deg + cvt_x + split_w1T + split_w2T ----------------
#define CD_BLOCKS 3321
#define SX_ITEMS (N_NODES * IN_F / 4)
#define SX_BLOCKS ((SX_ITEMS + 255) / 256)
#define SW1_ITEMS (HID_F * (IN_F / 2))         // 65536
#define SW1_BLOCKS (SW1_ITEMS / 256)
#define SW2_ITEMS (OUT_F * (HID_F / 2))        // 16384
#define SW2_BLOCKS (SW2_ITEMS / 256)
#define PREP_BLOCKS (CD_BLOCKS + SX_BLOCKS + SW1_BLOCKS + SW2_BLOCKS)

__global__ void prep_kernel(const float* __restrict__ x,
                            const float* __restrict__ W1,
                            const float* __restrict__ W2,
                            const int* __restrict__ edst) {
    int b = blockIdx.x;
    int tid = threadIdx.x;
    if (b < CD_BLOCKS) {
        int e = b * 256 + tid;
        if (e < N_EDGES) atomicAdd(&g_deg[edst[e]], 1);
        return;
    }
    b -= CD_BLOCKS;
    if (b < SX_BLOCKS) {
        int i = b * 256 + tid;
        if (i >= SX_ITEMS) return;
        float4 v = reinterpret_cast<const float4*>(x)[i];
        uint2 h;
        h.x = f16pair(v.x, v.y);
        h.y = f16pair(v.z, v.w);
        reinterpret_cast<uint2*>(g_xh)[i] = h;
        return;
    }
    b -= SX_BLOCKS;
    if (b < SW1_BLOCKS) {
        // W1^T: idx = n * K2 + k2, K2 = 256
        int idx = b * 256 + tid;
        int n = idx >> 8;
        int k2 = idx & 255;
        float a = W1[(size_t)(2 * k2) * HID_F + n];
        float c = W1[(size_t)(2 * k2 + 1) * HID_F + n];
        uint32_t lo;
        g_w1thi[idx] = split_pair_f16(a, c, lo);
        g_w1tlo[idx] = lo;
        return;
    }
    b -= SW1_BLOCKS;
    {
        // W2^T: idx = n * K2 + k2, K2 = 128
        int idx = b * 256 + tid;
        int n = idx >> 7;
        int k2 = idx & 127;
        float a = W2[(size_t)(2 * k2) * OUT_F + n];
        float c = W2[(size_t)(2 * k2 + 1) * OUT_F + n];
        uint32_t lo;
        g_w2thi[idx] = split_pair_f16(a, c, lo);
        g_w2tlo[idx] = lo;
    }
}

// single block, 1024 threads: exclusive scan of degrees -> rowptr, plus inv_deg
__global__ void scan_kernel() {
    __shared__ int partial[1024];
    const int tid = threadIdx.x;
    const int CH = (N_NODES + 1023) / 1024;
    int start = tid * CH;
    int stop = start + CH;
    if (stop > N_NODES) stop = N_NODES;
    int s = 0;
    for (int i = start; i < stop; ++i) s += g_deg[i];
    partial[tid] = s;
    __syncthreads();
    for (int off = 1; off < 1024; off <<= 1) {
        int v = 0;
        if (tid >= off) v = partial[tid - off];
        __syncthreads();
        partial[tid] += v;
        __syncthreads();
    }
    int base = partial[tid] - s;
    for (int i = start; i < stop; ++i) {
        int d = g_deg[i];
        g_rowptr[i] = base;
        base += d;
        g_invdeg[i] = 1.0f / (float)(d > 0 ? d : 1);
    }
    if (tid == 0) g_rowptr[N_NODES] = partial[1023];
}

__global__ void profile_marker_kernel() {}

// ---------------- fp16 2-term MMA GEMM with ldmatrix fragments ----------------
__device__ __forceinline__ void mma_f16(float* c, const uint32_t* a, const uint32_t* b) {
    asm volatile(
        "mma.sync.aligned.m16n8k16.row.col.f32.f16.f16.f32 "
        "{%0,%1,%2,%3}, {%4,%5,%6,%7}, {%8,%9}, {%0,%1,%2,%3};\n"
        : "+f"(c[0]), "+f"(c[1]), "+f"(c[2]), "+f"(c[3])
        : "r"(a[0]), "r"(a[1]), "r"(a[2]), "r"(a[3]), "r"(b[0]), "r"(b[1]));
}

__device__ __forceinline__ void ldmatrix_x4(uint32_t* r, uint32_t saddr) {
    asm volatile("ldmatrix.sync.aligned.m8n8.x4.shared.b16 {%0,%1,%2,%3}, [%4];"
                 : "=r"(r[0]), "=r"(r[1]), "=r"(r[2]), "=r"(r[3]) : "r"(saddr));
}

__device__ __forceinline__ void cp_async16(void* smem_dst, const void* gmem_src, int src_bytes) {
    uint32_t s = (uint32_t)__cvta_generic_to_shared(smem_dst);
    asm volatile("cp.async.cg.shared.global [%0], [%1], 16, %2;\n"
                 :: "r"(s), "l"(gmem_src), "r"(src_bytes));
}
__device__ __forceinline__ void cp_commit() { asm volatile("cp.async.commit_group;\n"); }
template <int N>
__device__ __forceinline__ void cp_wait() { asm volatile("cp.async.wait_group %0;\n" :: "n"(N)); }

#define BM 128
#define BN 128
#define BKP 16          // K-pairs per tile (= 32 fp16 elements)
#define ST 20           // tile row stride in u32 (16 data + 4 pad)
#define T_TILE (BM * ST)                     // 2560 u32 per tile buffer
#define SMEM_U32 (6 * T_TILE)                // A x2 bufs + B(hi/lo) x2 bufs = 61440 B
#define GEMM_ROWS ((N_NODES + BM - 1) / BM)  // 391

// A: [M][K2] u32 fp16-pairs. B: [N][K2] u32 (hi and lo arrays). Both K-pair packed.
// blocks with blockIdx.y >= gemm_rows run build_csr instead (one edge/thread).
__global__ __launch_bounds__(256, 2)
void gemm_f16_kernel(const uint32_t* __restrict__ Ah,
                     const uint32_t* __restrict__ Bh, const uint32_t* __restrict__ Bl,
                     uint32_t* __restrict__ Ch, int M, int K2, int N,
                     const int* __restrict__ esrc, const int* __restrict__ edst,
                     const float* __restrict__ ew, int gemm_rows) {
    extern __shared__ uint32_t smem[];
    const int tid = threadIdx.x;

    if ((int)blockIdx.y >= gemm_rows) {
        int lin = ((int)blockIdx.y - gemm_rows) * (int)gridDim.x + (int)blockIdx.x;
        int e = lin * 256 + tid;
        if (e < N_EDGES) {
            int dst = edst[e];
            int p = g_rowptr[dst] + atomicAdd(&g_pos[dst], 1);
            g_esrc[p] = esrc[e];
            g_ew[p] = ew[e];
        }
        return;
    }

    uint32_t* Abase = smem;                  // [buf][BM][ST]
    uint32_t* Bbase = smem + 2 * T_TILE;     // [buf][hl][BN][ST]
    const uint32_t smemByte = (uint32_t)__cvta_generic_to_shared(smem);

    const int wid = tid >> 5;
    const int lane = tid & 31;
    const int warp_m = wid >> 1;
    const int warp_n = wid & 1;
    const int m_base = warp_m * 32;
    const int n_base = warp_n * 64;
    const int blockRow = blockIdx.y * BM;
    const int blockCol = blockIdx.x * BN;
    const int ntiles = K2 / BKP;

    // ldmatrix per-lane offsets (u32 units within a tile buffer)
    // A x4: lanes 0-15 -> rows m0-15 at col jb; lanes 16-31 -> same rows at col jb+4
    const int aOff = (m_base + (lane & 15)) * ST + ((lane >> 4) << 2);
    // B x4: mat0 n0-7@jb, mat1 n0-7@jb+4, mat2 n8-15@jb, mat3 n8-15@jb+4
    const int bOff = (n_base + (lane & 7) + ((lane >> 4) << 3)) * ST + (((lane >> 3) & 1) << 2);

    float acc[2][8][4];
#pragma unroll
    for (int mt = 0; mt < 2; mt++)
#pragma unroll
        for (int nt = 0; nt < 8; nt++)
#pragma unroll
            for (int i = 0; i < 4; i++) acc[mt][nt][i] = 0.0f;

    auto load_tiles = [&](int t, int buf) {
        const int k0p = t * BKP;
        // A tile: 128 rows x 16 u32 = 512 x 16B, 2 iterations
        uint32_t* Asb = Abase + buf * T_TILE;
#pragma unroll
        for (int i = 0; i < 2; i++) {
            int idx = tid + i * 256;
            int row = idx >> 2;
            int c4 = idx & 3;
            int gr = blockRow + row;
            int inb = (gr < M);
            int grc = inb ? gr : 0;
            cp_async16(&Asb[row * ST + c4 * 4],
                       Ah + (size_t)grc * K2 + k0p + c4 * 4, inb ? 16 : 0);
        }
        // B tiles (hi, lo): 128 rows x 16 u32 each, 2 iterations each
        const uint32_t* Bg[2] = {Bh, Bl};
#pragma unroll
        for (int hl = 0; hl < 2; hl++) {
            uint32_t* Bsb = Bbase + (buf * 2 + hl) * T_TILE;
#pragma unroll
            for (int i = 0; i < 2; i++) {
                int idx = tid + i * 256;
                int row = idx >> 2;
                int c4 = idx & 3;
                cp_async16(&Bsb[row * ST + c4 * 4],
                           Bg[hl] + (size_t)(blockCol + row) * K2 + k0p + c4 * 4, 16);
            }
        }
    };

    load_tiles(0, 0);
    cp_commit();

    for (int t = 0; t < ntiles; ++t) {
        const int buf = t & 1;
        if (t + 1 < ntiles) {
            load_tiles(t + 1, (t + 1) & 1);
            cp_commit();
            cp_wait<1>();
        } else {
            cp_wait<0>();
        }
        __syncthreads();

        const int aTile = buf * T_TILE;
        const int bhTile = 2 * T_TILE + (buf * 2 + 0) * T_TILE;
        const int blTile = 2 * T_TILE + (buf * 2 + 1) * T_TILE;

#pragma unroll
        for (int kk = 0; kk < 2; kk++) {
            const int jb = kk * 8;
            uint32_t ah[2][4];
#pragma unroll
            for (int mt = 0; mt < 2; mt++) {
                ldmatrix_x4(ah[mt], smemByte + 4u * (aTile + aOff + mt * 16 * ST + jb));
            }
            uint32_t bh[8][2], bl[8][2];
#pragma unroll
            for (int ntp = 0; ntp < 4; ntp++) {
                ldmatrix_x4(&bh[2 * ntp][0], smemByte + 4u * (bhTile + bOff + ntp * 16 * ST + jb));
                ldmatrix_x4(&bl[2 * ntp][0], smemByte + 4u * (blTile + bOff + ntp * 16 * ST + jb));
            }
#pragma unroll
            for (int mt = 0; mt < 2; mt++) {
#pragma unroll
                for (int nt = 0; nt < 8; nt++) {
                    mma_f16(acc[mt][nt], ah[mt], bh[nt]);   // a * w_hi
                    mma_f16(acc[mt][nt], ah[mt], bl[nt]);   // a * w_lo
                }
            }
        }
        __syncthreads();
    }

    // epilogue: pack adjacent column pairs to fp16x2
    const int gid = lane >> 2;
    const int tig = lane & 3;
#pragma unroll
    for (int mt = 0; mt < 2; mt++) {
#pragma unroll
        for (int nt = 0; nt < 8; nt++) {
            int r = blockRow + m_base + mt * 16 + gid;
            int c = blockCol + n_base + nt * 8 + tig * 2;
            if (r < M) {
                Ch[((size_t)r * N + c) >> 1] = f16pair(acc[mt][nt][0], acc[mt][nt][1]);
            }
            if (r + 8 < M) {
                Ch[((size_t)(r + 8) * N + c) >> 1] = f16pair(acc[mt][nt][2], acc[mt][nt][3]);
            }
        }
    }
}

// ---------------- gather-side aggregation (fp16 features, f32 accum) ----------------
__device__ __forceinline__ void acc_fma8(float* a, uint4 v, float w) {
    float2 p;
    p = __half22float2(*reinterpret_cast<__half2*>(&v.x)); a[0] += w * p.x; a[1] += w * p.y;
    p = __half22float2(*reinterpret_cast<__half2*>(&v.y)); a[2] += w * p.x; a[3] += w * p.y;
    p = __half22float2(*reinterpret_cast<__half2*>(&v.z)); a[4] += w * p.x; a[5] += w * p.y;
    p = __half22float2(*reinterpret_cast<__half2*>(&v.w)); a[6] += w * p.x; a[7] += w * p.y;
}

// Layer 1: 256 fp16 feats/node = one uint4 per lane. One warp per node.
__global__ void aggregate1_kernel(const float* __restrict__ bias) {
    int gw = (blockIdx.x * blockDim.x + threadIdx.x) >> 5;
    int lane = threadIdx.x & 31;
    if (gw >= N_NODES) return;
    int beg = g_rowptr[gw], end = g_rowptr[gw + 1];

    float a[8];
#pragma unroll
    for (int i = 0; i < 8; i++) a[i] = 0.0f;

    const uint4* feat = reinterpret_cast<const uint4*>(g_hw1h);
    int e = beg;
    for (; e + 1 < end; e += 2) {
        int s0 = g_esrc[e];
        int s1 = g_esrc[e + 1];
        float w0 = g_ew[e];
        float w1 = g_ew[e + 1];
        uint4 v0 = __ldg(feat + (size_t)s0 * 32 + lane);
        uint4 v1 = __ldg(feat + (size_t)s1 * 32 + lane);
        acc_fma8(a, v0, w0);
        acc_fma8(a, v1, w1);
    }
    if (e < end) {
        int s0 = g_esrc[e];
        float w0 = g_ew[e];
        uint4 v0 = __ldg(feat + (size_t)s0 * 32 + lane);
        acc_fma8(a, v0, w0);
    }

    float inv = g_invdeg[gw];
    const float4* bp = reinterpret_cast<const float4*>(bias);
    float4 bA = bp[lane * 2];
    float4 bB = bp[lane * 2 + 1];
    float o[8];
    o[0] = fmaxf(a[0] * inv + bA.x, 0.f);
    o[1] = fmaxf(a[1] * inv + bA.y, 0.f);
    o[2] = fmaxf(a[2] * inv + bA.z, 0.f);
    o[3] = fmaxf(a[3] * inv + bA.w, 0.f);
    o[4] = fmaxf(a[4] * inv + bB.x, 0.f);
    o[5] = fmaxf(a[5] * inv + bB.y, 0.f);
    o[6] = fmaxf(a[6] * inv + bB.z, 0.f);
    o[7] = fmaxf(a[7] * inv + bB.w, 0.f);

    uint4 ph;
    ph.x = f16pair(o[0], o[1]);
    ph.y = f16pair(o[2], o[3]);
    ph.z = f16pair(o[4], o[5]);
    ph.w = f16pair(o[6], o[7]);
    reinterpret_cast<uint4*>(g_hh)[(size_t)gw * 32 + lane] = ph;
}

// Layer 2: 128 fp16 feats/node = one uint2 per lane. One warp per node.
__global__ void aggregate2_kernel(const float* __restrict__ bias, float* __restrict__ out) {
    int gw = (blockIdx.x * blockDim.x + threadIdx.x) >> 5;
    int lane = threadIdx.x & 31;
    if (gw >= N_NODES) return;
    int beg = g_rowptr[gw], end = g_rowptr[gw + 1];

    float a[4];
#pragma unroll
    for (int i = 0; i < 4; i++) a[i] = 0.0f;

    const uint2* feat = reinterpret_cast<const uint2*>(g_hw2h);
    int e = beg;
    for (; e + 1 < end; e += 2) {
        int s0 = g_esrc[e];
        int s1 = g_esrc[e + 1];
        float w0 = g_ew[e];
        float w1 = g_ew[e + 1];
        uint2 v0 = __ldg(feat + (size_t)s0 * 32 + lane);
        uint2 v1 = __ldg(feat + (size_t)s1 * 32 + lane);
        float2 p;
        p = __half22float2(*reinterpret_cast<__half2*>(&v0.x)); a[0] += w0 * p.x; a[1] += w0 * p.y;
        p = __half22float2(*reinterpret_cast<__half2*>(&v0.y)); a[2] += w0 * p.x; a[3] += w0 * p.y;
        p = __half22float2(*reinterpret_cast<__half2*>(&v1.x)); a[0] += w1 * p.x; a[1] += w1 * p.y;
        p = __half22float2(*reinterpret_cast<__half2*>(&v1.y)); a[2] += w1 * p.x; a[3] += w1 * p.y;
    }
    if (e < end) {
        int s0 = g_esrc[e];
        float w0 = g_ew[e];
        uint2 v0 = __ldg(feat + (size_t)s0 * 32 + lane);
        float2 p;
        p = __half22float2(*reinterpret_cast<__half2*>(&v0.x)); a[0] += w0 * p.x; a[1] += w0 * p.y;
        p = __half22float2(*reinterpret_cast<__half2*>(&v0.y)); a[2] += w0 * p.x; a[3] += w0 * p.y;
    }

    float inv = g_invdeg[gw];
    float4 b0 = reinterpret_cast<const float4*>(bias)[lane];
    float4 o0;
    o0.x = a[0] * inv + b0.x;
    o0.y = a[1] * inv + b0.y;
    o0.z = a[2] * inv + b0.z;
    o0.w = a[3] * inv + b0.w;
    reinterpret_cast<float4*>(out)[(size_t)gw * 32 + lane] = o0;
}

// ---------------- launch ----------------
extern "C" void kernel_launch(void* const* d_in, const int* in_sizes, int n_in,
                              void* d_out, int out_size) {
    const float* x    = (const float*)d_in[0];
    const float* W1   = (const float*)d_in[1];
    const float* b1   = (const float*)d_in[2];
    const float* W2   = (const float*)d_in[3];
    const float* b2   = (const float*)d_in[4];
    const float* ew   = (const float*)d_in[5];
    const int*   esrc = (const int*)d_in[6];
    const int*   edst = (const int*)d_in[7];
    float* out = (float*)d_out;

    void *p_hw1h, *p_hw2h, *p_xh, *p_hh;
    void *p_w1thi, *p_w1tlo, *p_w2thi, *p_w2tlo, *p_deg, *p_pos;
    cudaGetSymbolAddress(&p_hw1h, g_hw1h);
    cudaGetSymbolAddress(&p_hw2h, g_hw2h);
    cudaGetSymbolAddress(&p_xh, g_xh);
    cudaGetSymbolAddress(&p_hh, g_hh);
    cudaGetSymbolAddress(&p_w1thi, g_w1thi);
    cudaGetSymbolAddress(&p_w1tlo, g_w1tlo);
    cudaGetSymbolAddress(&p_w2thi, g_w2thi);
    cudaGetSymbolAddress(&p_w2tlo, g_w2tlo);
    cudaGetSymbolAddress(&p_deg, g_deg);
    cudaGetSymbolAddress(&p_pos, g_pos);

    cudaFuncSetAttribute(gemm_f16_kernel,
                         cudaFuncAttributeMaxDynamicSharedMemorySize, SMEM_U32 * 4);

    cudaMemsetAsync(p_deg, 0, N_NODES * sizeof(int));          // launch 1
    cudaMemsetAsync(p_pos, 0, N_NODES * sizeof(int));          // launch 2

    prep_kernel<<<PREP_BLOCKS, 256>>>(x, W1, W2, edst);        // launch 3
    scan_kernel<<<1, 1024>>>();                                // launch 4
    profile_marker_kernel<<<1, 32>>>();                        // launch 5

    // GEMM1: hw1 = x @ W1 -> fp16, with build_csr fused      (launch 6 -> ncu)
    {
        const int CSR_ROWS = (N_EDGES + 2 * 256 - 1) / (2 * 256);  // 1661 (gridDim.x = 2)
        dim3 grid(HID_F / BN, GEMM_ROWS + CSR_ROWS);
        gemm_f16_kernel<<<grid, 256, SMEM_U32 * 4>>>(
            (const uint32_t*)p_xh,
            (const uint32_t*)p_w1thi, (const uint32_t*)p_w1tlo,
            (uint32_t*)p_hw1h, N_NODES, IN_F / 2, HID_F,
            esrc, edst, ew, GEMM_ROWS);
    }

    // agg1: h = relu(agg(hw1)*invdeg + b1) -> fp16           (launch 7)
    aggregate1_kernel<<<(N_NODES * 32 + 255) / 256, 256>>>(b1);

    // GEMM2: hw2 = h @ W2 -> fp16                             (launch 8)
    gemm_f16_kernel<<<dim3(OUT_F / BN, GEMM_ROWS), 256, SMEM_U32 * 4>>>(
        (const uint32_t*)p_hh,
        (const uint32_t*)p_w2thi, (const uint32_t*)p_w2tlo,
        (uint32_t*)p_hw2h, N_NODES, HID_F / 2, OUT_F,
        nullptr, nullptr, nullptr, GEMM_ROWS);

    // agg2: out = agg(hw2)*invdeg + b2                        (launch 9)
    aggregate2_kernel<<<(N_NODES * 32 + 255) / 256, 256>>>(b2, out);
}

// round 17
// speedup vs baseline: 1.1302x; 1.1302x over previous
#include <cuda_runtime.h>
#include <cuda_bf16.h>
#include <cuda_fp16.h>
#include <cstdint>

#define N_NODES 50000
#define N_EDGES 850000
#define IN_F 512
#define HID_F 256
#define OUT_F 128

// ---------------- device scratch ----------------
__device__ uint32_t g_hw1h[N_NODES * HID_F / 2];   // x @ W1, fp16x2 packed
__device__ uint32_t g_hw2h[N_NODES * OUT_F / 2];   // h @ W2, fp16x2 packed
__device__ uint32_t g_xh[N_NODES * IN_F / 2];      // x as fp16x2 pairs along K
__device__ uint32_t g_hh[N_NODES * HID_F / 2];     // h as fp16x2 (written by agg1)
__device__ uint32_t g_w1h[(IN_F / 2) * HID_F];     // W1 k-pair-interleaved fp16
__device__ uint32_t g_w2h[(HID_F / 2) * OUT_F];    // W2 k-pair-interleaved fp16
__device__ float    g_invdeg[N_NODES];
__device__ int      g_deg[N_NODES];
__device__ int      g_rowptr[N_NODES + 1];
__device__ int      g_pos[N_NODES];
__device__ int      g_esrc[N_EDGES];
__device__ float    g_ew[N_EDGES];

// ---------------- fp16 helpers ----------------
__device__ __forceinline__ uint32_t f16pair(float a, float b) {
    __half2 p = __floats2half2_rn(a, b);
    return *reinterpret_cast<uint32_t*>(&p);
}

// ---------------- fused prep: count_deg + cvt_x + cvt_w1 + cvt_w2 ----------------
#define CD_BLOCKS 3321     // ceil(850000 / 256)
#define SX_ITEMS (N_NODES * IN_F / 4)          // 6.4M float4
#define SX_BLOCKS ((SX_ITEMS + 255) / 256)
#define SW1_ITEMS ((IN_F / 2) * HID_F)         // 65536
#define SW1_BLOCKS (SW1_ITEMS / 256)
#define SW2_ITEMS ((HID_F / 2) * OUT_F)        // 16384
#define SW2_BLOCKS (SW2_ITEMS / 256)
#define PREP_BLOCKS (CD_BLOCKS + SX_BLOCKS + SW1_BLOCKS + SW2_BLOCKS)

__global__ void prep_kernel(const float* __restrict__ x,
                            const float* __restrict__ W1,
                            const float* __restrict__ W2,
                            const int* __restrict__ edst) {
    int b = blockIdx.x;
    int tid = threadIdx.x;
    if (b < CD_BLOCKS) {
        int e = b * 256 + tid;
        if (e < N_EDGES) atomicAdd(&g_deg[edst[e]], 1);
        return;
    }
    b -= CD_BLOCKS;
    if (b < SX_BLOCKS) {
        int i = b * 256 + tid;               // float4 index
        if (i >= SX_ITEMS) return;
        float4 v = reinterpret_cast<const float4*>(x)[i];
        uint2 h;
        h.x = f16pair(v.x, v.y);
        h.y = f16pair(v.z, v.w);
        reinterpret_cast<uint2*>(g_xh)[i] = h;
        return;
    }
    b -= SX_BLOCKS;
    if (b < SW1_BLOCKS) {
        int idx = b * 256 + tid;             // u32 index, [K2][N] layout
        int k2 = idx >> 8;                   // / HID_F
        int n = idx & (HID_F - 1);
        float a = W1[(size_t)(2 * k2) * HID_F + n];
        float c = W1[(size_t)(2 * k2 + 1) * HID_F + n];
        g_w1h[idx] = f16pair(a, c);
        return;
    }
    b -= SW1_BLOCKS;
    {
        int idx = b * 256 + tid;
        int k2 = idx >> 7;                   // / OUT_F
        int n = idx & (OUT_F - 1);
        float a = W2[(size_t)(2 * k2) * OUT_F + n];
        float c = W2[(size_t)(2 * k2 + 1) * OUT_F + n];
        g_w2h[idx] = f16pair(a, c);
    }
}

// single block, 1024 threads: exclusive scan of degrees -> rowptr, plus inv_deg
__global__ void scan_kernel() {
    __shared__ int partial[1024];
    const int tid = threadIdx.x;
    const int CH = (N_NODES + 1023) / 1024;
    int start = tid * CH;
    int stop = start + CH;
    if (stop > N_NODES) stop = N_NODES;
    int s = 0;
    for (int i = start; i < stop; ++i) s += g_deg[i];
    partial[tid] = s;
    __syncthreads();
    for (int off = 1; off < 1024; off <<= 1) {
        int v = 0;
        if (tid >= off) v = partial[tid - off];
        __syncthreads();
        partial[tid] += v;
        __syncthreads();
    }
    int base = partial[tid] - s;
    for (int i = start; i < stop; ++i) {
        int d = g_deg[i];
        g_rowptr[i] = base;
        base += d;
        g_invdeg[i] = 1.0f / (float)(d > 0 ? d : 1);
    }
    if (tid == 0) g_rowptr[N_NODES] = partial[1023];
}

__global__ void profile_marker_kernel() {}

// ---------------- fp16 MMA GEMM (single-term) + fused build_csr blocks ----------------
__device__ __forceinline__ void mma_f16(float* c, const uint32_t* a, const uint32_t* b) {
    asm volatile(
        "mma.sync.aligned.m16n8k16.row.col.f32.f16.f16.f32 "
        "{%0,%1,%2,%3}, {%4,%5,%6,%7}, {%8,%9}, {%0,%1,%2,%3};\n"
        : "+f"(c[0]), "+f"(c[1]), "+f"(c[2]), "+f"(c[3])
        : "r"(a[0]), "r"(a[1]), "r"(a[2]), "r"(a[3]), "r"(b[0]), "r"(b[1]));
}

__device__ __forceinline__ void cp_async16(void* smem_dst, const void* gmem_src, int src_bytes) {
    uint32_t s = (uint32_t)__cvta_generic_to_shared(smem_dst);
    asm volatile("cp.async.cg.shared.global [%0], [%1], 16, %2;\n"
                 :: "r"(s), "l"(gmem_src), "r"(src_bytes));
}
__device__ __forceinline__ void cp_commit() { asm volatile("cp.async.commit_group;\n"); }
template <int N>
__device__ __forceinline__ void cp_wait() { asm volatile("cp.async.wait_group %0;\n" :: "n"(N)); }

#define BM 128
#define BN 128
#define BKP 16          // K-pairs per tile (= 32 fp16 elements)
#define SA 20           // A row stride in u32
#define SB 136          // B row stride in u32
#define A_TILE (BM * SA)                     // 2560 u32
#define B_TILE (BKP * SB)                    // 2176 u32
#define SMEM_U32 (2 * A_TILE + 2 * B_TILE)   // 9472 u32 = 37888 B
#define GEMM_ROWS ((N_NODES + BM - 1) / BM)  // 391

// A: [M][K2] u32 fp16-pairs row-major. B: [K2][N] u32 k-pair-interleaved fp16.
// blocks with blockIdx.y >= gemm_rows run build_csr instead (one edge/thread).
__global__ __launch_bounds__(256, 2)
void gemm_f16_kernel(const uint32_t* __restrict__ Ah,
                     const uint32_t* __restrict__ Bh,
                     uint32_t* __restrict__ Ch, int M, int K2, int N,
                     const int* __restrict__ esrc, const int* __restrict__ edst,
                     const float* __restrict__ ew, int gemm_rows) {
    extern __shared__ uint32_t smem[];
    const int tid = threadIdx.x;

    if ((int)blockIdx.y >= gemm_rows) {
        // ---- build_csr part ----
        int lin = ((int)blockIdx.y - gemm_rows) * (int)gridDim.x + (int)blockIdx.x;
        int e = lin * 256 + tid;
        if (e < N_EDGES) {
            int dst = edst[e];
            int p = g_rowptr[dst] + atomicAdd(&g_pos[dst], 1);
            g_esrc[p] = esrc[e];
            g_ew[p] = ew[e];
        }
        return;
    }

    uint32_t* Abase = smem;                  // [buf][BM][SA]
    uint32_t* Bbase = smem + 2 * A_TILE;     // [buf][BKP][SB]

    const int wid = tid >> 5;
    const int lane = tid & 31;
    const int gid = lane >> 2;
    const int tig = lane & 3;
    const int warp_m = wid >> 1;
    const int warp_n = wid & 1;
    const int m_base = warp_m * 32;
    const int n_base = warp_n * 64;
    const int blockRow = blockIdx.y * BM;
    const int blockCol = blockIdx.x * BN;
    const int ntiles = K2 / BKP;

    float acc[2][8][4];
#pragma unroll
    for (int mt = 0; mt < 2; mt++)
#pragma unroll
        for (int nt = 0; nt < 8; nt++)
#pragma unroll
            for (int i = 0; i < 4; i++) acc[mt][nt][i] = 0.0f;

    auto load_tiles = [&](int t, int buf) {
        const int k0p = t * BKP;
        // A tile: 128 rows x 16 u32 = 512 x 16B, 2 iterations
        uint32_t* Asb = Abase + buf * A_TILE;
#pragma unroll
        for (int i = 0; i < 2; i++) {
            int idx = tid + i * 256;
            int row = idx >> 2;
            int c4 = idx & 3;
            int gr = blockRow + row;
            int inb = (gr < M);
            int grc = inb ? gr : 0;
            cp_async16(&Asb[row * SA + c4 * 4],
                       Ah + (size_t)grc * K2 + k0p + c4 * 4, inb ? 16 : 0);
        }
        // B tile: 16 rows x 128 u32 = 512 x 16B, 2 iterations
        uint32_t* Bsb = Bbase + buf * B_TILE;
#pragma unroll
        for (int i = 0; i < 2; i++) {
            int idx = tid + i * 256;
            int row = idx >> 5;
            int c4 = idx & 31;
            cp_async16(&Bsb[row * SB + c4 * 4],
                       Bh + (size_t)(k0p + row) * N + blockCol + c4 * 4, 16);
        }
    };

    load_tiles(0, 0);
    cp_commit();

    for (int t = 0; t < ntiles; ++t) {
        const int buf = t & 1;
        if (t + 1 < ntiles) {
            load_tiles(t + 1, (t + 1) & 1);
            cp_commit();
            cp_wait<1>();
        } else {
            cp_wait<0>();
        }
        __syncthreads();

        const uint32_t* A_s = Abase + buf * A_TILE;
        const uint32_t* B_s = Bbase + buf * B_TILE;

#pragma unroll
        for (int kk = 0; kk < 2; kk++) {
            const int jb = kk * 8;
            uint32_t ah[2][4];
#pragma unroll
            for (int mt = 0; mt < 2; mt++) {
                int r0 = m_base + mt * 16 + gid;
                int o0 = r0 * SA + jb + tig;
                int o1 = (r0 + 8) * SA + jb + tig;
                ah[mt][0] = A_s[o0];
                ah[mt][1] = A_s[o1];
                ah[mt][2] = A_s[o0 + 4];
                ah[mt][3] = A_s[o1 + 4];
            }
            uint32_t bh[8][2];
#pragma unroll
            for (int nt = 0; nt < 8; nt++) {
                int col = n_base + nt * 8 + gid;
                bh[nt][0] = B_s[(jb + tig) * SB + col];
                bh[nt][1] = B_s[(jb + tig + 4) * SB + col];
            }
#pragma unroll
            for (int mt = 0; mt < 2; mt++) {
#pragma unroll
                for (int nt = 0; nt < 8; nt++) {
                    mma_f16(acc[mt][nt], ah[mt], bh[nt]);
                }
            }
        }
        __syncthreads();
    }

    // epilogue: pack adjacent column pairs to fp16x2
#pragma unroll
    for (int mt = 0; mt < 2; mt++) {
#pragma unroll
        for (int nt = 0; nt < 8; nt++) {
            int r = blockRow + m_base + mt * 16 + gid;
            int c = blockCol + n_base + nt * 8 + tig * 2;
            if (r < M) {
                Ch[((size_t)r * N + c) >> 1] = f16pair(acc[mt][nt][0], acc[mt][nt][1]);
            }
            if (r + 8 < M) {
                Ch[((size_t)(r + 8) * N + c) >> 1] = f16pair(acc[mt][nt][2], acc[mt][nt][3]);
            }
        }
    }
}

// ---------------- gather-side aggregation (fp16 features, f32 accum) ----------------
__device__ __forceinline__ void acc_fma8(float* a, uint4 v, float w) {
    float2 p;
    p = __half22float2(*reinterpret_cast<__half2*>(&v.x)); a[0] += w * p.x; a[1] += w * p.y;
    p = __half22float2(*reinterpret_cast<__half2*>(&v.y)); a[2] += w * p.x; a[3] += w * p.y;
    p = __half22float2(*reinterpret_cast<__half2*>(&v.z)); a[4] += w * p.x; a[5] += w * p.y;
    p = __half22float2(*reinterpret_cast<__half2*>(&v.w)); a[6] += w * p.x; a[7] += w * p.y;
}

// Layer 1: 256 fp16 feats/node = one uint4 per lane. One warp per node.
__global__ void aggregate1_kernel(const float* __restrict__ bias) {
    int gw = (blockIdx.x * blockDim.x + threadIdx.x) >> 5;
    int lane = threadIdx.x & 31;
    if (gw >= N_NODES) return;
    int beg = g_rowptr[gw], end = g_rowptr[gw + 1];

    float a[8];
#pragma unroll
    for (int i = 0; i < 8; i++) a[i] = 0.0f;

    const uint4* feat = reinterpret_cast<const uint4*>(g_hw1h);
    int e = beg;
    for (; e + 1 < end; e += 2) {
        int s0 = g_esrc[e];
        int s1 = g_esrc[e + 1];
        float w0 = g_ew[e];
        float w1 = g_ew[e + 1];
        uint4 v0 = __ldg(feat + (size_t)s0 * 32 + lane);
        uint4 v1 = __ldg(feat + (size_t)s1 * 32 + lane);
        acc_fma8(a, v0, w0);
        acc_fma8(a, v1, w1);
    }
    if (e < end) {
        int s0 = g_esrc[e];
        float w0 = g_ew[e];
        uint4 v0 = __ldg(feat + (size_t)s0 * 32 + lane);
        acc_fma8(a, v0, w0);
    }

    float inv = g_invdeg[gw];
    const float4* bp = reinterpret_cast<const float4*>(bias);
    float4 bA = bp[lane * 2];
    float4 bB = bp[lane * 2 + 1];
    float o[8];
    o[0] = fmaxf(a[0] * inv + bA.x, 0.f);
    o[1] = fmaxf(a[1] * inv + bA.y, 0.f);
    o[2] = fmaxf(a[2] * inv + bA.z, 0.f);
    o[3] = fmaxf(a[3] * inv + bA.w, 0.f);
    o[4] = fmaxf(a[4] * inv + bB.x, 0.f);
    o[5] = fmaxf(a[5] * inv + bB.y, 0.f);
    o[6] = fmaxf(a[6] * inv + bB.z, 0.f);
    o[7] = fmaxf(a[7] * inv + bB.w, 0.f);

    uint4 ph;
    ph.x = f16pair(o[0], o[1]);
    ph.y = f16pair(o[2], o[3]);
    ph.z = f16pair(o[4], o[5]);
    ph.w = f16pair(o[6], o[7]);
    reinterpret_cast<uint4*>(g_hh)[(size_t)gw * 32 + lane] = ph;
}

// Layer 2: 128 fp16 feats/node = one uint2 per lane. One warp per node.
__global__ void aggregate2_kernel(const float* __restrict__ bias, float* __restrict__ out) {
    int gw = (blockIdx.x * blockDim.x + threadIdx.x) >> 5;
    int lane = threadIdx.x & 31;
    if (gw >= N_NODES) return;
    int beg = g_rowptr[gw], end = g_rowptr[gw + 1];

    float a[4];
#pragma unroll
    for (int i = 0; i < 4; i++) a[i] = 0.0f;

    const uint2* feat = reinterpret_cast<const uint2*>(g_hw2h);
    int e = beg;
    for (; e + 1 < end; e += 2) {
        int s0 = g_esrc[e];
        int s1 = g_esrc[e + 1];
        float w0 = g_ew[e];
        float w1 = g_ew[e + 1];
        uint2 v0 = __ldg(feat + (size_t)s0 * 32 + lane);
        uint2 v1 = __ldg(feat + (size_t)s1 * 32 + lane);
        float2 p;
        p = __half22float2(*reinterpret_cast<__half2*>(&v0.x)); a[0] += w0 * p.x; a[1] += w0 * p.y;
        p = __half22float2(*reinterpret_cast<__half2*>(&v0.y)); a[2] += w0 * p.x; a[3] += w0 * p.y;
        p = __half22float2(*reinterpret_cast<__half2*>(&v1.x)); a[0] += w1 * p.x; a[1] += w1 * p.y;
        p = __half22float2(*reinterpret_cast<__half2*>(&v1.y)); a[2] += w1 * p.x; a[3] += w1 * p.y;
    }
    if (e < end) {
        int s0 = g_esrc[e];
        float w0 = g_ew[e];
        uint2 v0 = __ldg(feat + (size_t)s0 * 32 + lane);
        float2 p;
        p = __half22float2(*reinterpret_cast<__half2*>(&v0.x)); a[0] += w0 * p.x; a[1] += w0 * p.y;
        p = __half22float2(*reinterpret_cast<__half2*>(&v0.y)); a[2] += w0 * p.x; a[3] += w0 * p.y;
    }

    float inv = g_invdeg[gw];
    float4 b0 = reinterpret_cast<const float4*>(bias)[lane];
    float4 o0;
    o0.x = a[0] * inv + b0.x;
    o0.y = a[1] * inv + b0.y;
    o0.z = a[2] * inv + b0.z;
    o0.w = a[3] * inv + b0.w;
    reinterpret_cast<float4*>(out)[(size_t)gw * 32 + lane] = o0;
}

// ---------------- launch ----------------
extern "C" void kernel_launch(void* const* d_in, const int* in_sizes, int n_in,
                              void* d_out, int out_size) {
    const float* x    = (const float*)d_in[0];
    const float* W1   = (const float*)d_in[1];
    const float* b1   = (const float*)d_in[2];
    const float* W2   = (const float*)d_in[3];
    const float* b2   = (const float*)d_in[4];
    const float* ew   = (const float*)d_in[5];
    const int*   esrc = (const int*)d_in[6];
    const int*   edst = (const int*)d_in[7];
    float* out = (float*)d_out;

    void *p_hw1h, *p_hw2h, *p_xh, *p_hh;
    void *p_w1h, *p_w2h, *p_deg, *p_pos;
    cudaGetSymbolAddress(&p_hw1h, g_hw1h);
    cudaGetSymbolAddress(&p_hw2h, g_hw2h);
    cudaGetSymbolAddress(&p_xh, g_xh);
    cudaGetSymbolAddress(&p_hh, g_hh);
    cudaGetSymbolAddress(&p_w1h, g_w1h);
    cudaGetSymbolAddress(&p_w2h, g_w2h);
    cudaGetSymbolAddress(&p_deg, g_deg);
    cudaGetSymbolAddress(&p_pos, g_pos);

    cudaFuncSetAttribute(gemm_f16_kernel,
                         cudaFuncAttributeMaxDynamicSharedMemorySize, SMEM_U32 * 4);

    cudaMemsetAsync(p_deg, 0, N_NODES * sizeof(int));          // launch 1
    cudaMemsetAsync(p_pos, 0, N_NODES * sizeof(int));          // launch 2

    prep_kernel<<<PREP_BLOCKS, 256>>>(x, W1, W2, edst);        // launch 3
    scan_kernel<<<1, 1024>>>();                                // launch 4
    profile_marker_kernel<<<1, 32>>>();                        // launch 5

    // GEMM1: hw1 = x @ W1 -> fp16, with build_csr fused      (launch 6 -> ncu)
    {
        const int CSR_ROWS = (N_EDGES + 2 * 256 - 1) / (2 * 256);  // 1661 (gridDim.x = 2)
        dim3 grid(HID_F / BN, GEMM_ROWS + CSR_ROWS);
        gemm_f16_kernel<<<grid, 256, SMEM_U32 * 4>>>(
            (const uint32_t*)p_xh,
            (const uint32_t*)p_w1h,
            (uint32_t*)p_hw1h, N_NODES, IN_F / 2, HID_F,
            esrc, edst, ew, GEMM_ROWS);
    }

    // agg1: h = relu(agg(hw1)*invdeg + b1) -> fp16           (launch 7)
    aggregate1_kernel<<<(N_NODES * 32 + 255) / 256, 256>>>(b1);

    // GEMM2: hw2 = h @ W2 -> fp16                             (launch 8)
    gemm_f16_kernel<<<dim3(OUT_F / BN, GEMM_ROWS), 256, SMEM_U32 * 4>>>(
        (const uint32_t*)p_hh,
        (const uint32_t*)p_w2h,
        (uint32_t*)p_hw2h, N_NODES, HID_F / 2, OUT_F,
        nullptr, nullptr, nullptr, GEMM_ROWS);

    // agg2: out = agg(hw2)*invdeg + b2                        (launch 9)
    aggregate2_kernel<<<(N_NODES * 32 + 255) / 256, 256>>>(b2, out);
}